// round 15
// baseline (speedup 1.0000x reference)
#include <cuda_runtime.h>
#include <cuda_bf16.h>

// DataWindowLoss: mean(|box5(x) - box5(y)|), x,y: [64,1,512,512] f32.
// box5(x)-box5(y) = box5(x-y); separable 5x5 uniform kernel.
// Split-kernel register streaming: interior kernel has ONLY the hot loop
// (launch_bounds(128,6) -> 85-reg budget so ptxas does NOT serialize the
// prefetch rings: g-stream depth 4, g-1 stream depth 2, all true MLP).
// g-1 stream = same pointer, offset -1 group (in-bounds for interior
// chunks; masked for lane g==0). Boundary chunks + cols 512..515 live in
// a second small kernel. Shared accumulator + block counter finalizes.

#define B_IMGS 64
#define H 512
#define W 512
#define W4 128
#define OH 516
#define OW 516

#define THREADS 128
#define CHUNK_ROWS 16
#define SCAN 20
#define NCHUNK 33                         // chunks 0..32; interior = 1..31
#define NICHUNK 31
#define NBLOCKS_A (NICHUNK * B_IMGS)      // 1984
#define NBLOCKS_B (3 * B_IMGS)            // 192 (2 boundary + 1 edge per img)
#define NBLOCKS_T (NBLOCKS_A + NBLOCKS_B) // 2176

__device__ double g_accum;      // zero-initialized
__device__ unsigned g_count;    // zero-initialized

__device__ __forceinline__ float warp_red(float v) {
    #pragma unroll
    for (int o = 16; o > 0; o >>= 1) v += __shfl_down_sync(0xffffffffu, v, o);
    return v;
}

__device__ __forceinline__ float4 f4zero() { return make_float4(0.f, 0.f, 0.f, 0.f); }

// shared tail: block reduce + global accumulate + last-block finalize
__device__ __forceinline__ void reduce_finalize(float acc, int tid, int lane,
                                                float* __restrict__ out) {
    __shared__ float wsum[THREADS / 32];
    acc = warp_red(acc);
    if (lane == 0) wsum[tid >> 5] = acc;
    __syncthreads();
    if (tid == 0) {
        float v = 0.f;
        #pragma unroll
        for (int i = 0; i < THREADS / 32; ++i) v += wsum[i];
        atomicAdd(&g_accum, (double)v);
        __threadfence();
        unsigned prev_cnt = atomicAdd(&g_count, 1u);
        if (prev_cnt == NBLOCKS_T - 1) {
            __threadfence();
            double total = atomicAdd(&g_accum, 0.0);
            const double scale = 1.0 / (25.0 * (double)B_IMGS * (double)OH * (double)OW);
            out[0] = (float)(total * scale);
            g_accum = 0.0;          // reset for next graph replay
            __threadfence();
            g_count = 0u;
        }
    }
}

// ================= interior kernel: hot loop only =================
__global__ void __launch_bounds__(THREADS, 6)
box_interior_kernel(const float* __restrict__ x, const float* __restrict__ y,
                    float* __restrict__ out) {
    const int tid  = threadIdx.x;
    const int lane = tid & 31;
    const int img  = blockIdx.y;
    const size_t ibase = (size_t)img * H * W4;

    const int g      = tid;
    const int R0     = (blockIdx.x + 1) * CHUNK_ROWS;   // ci = 1..31
    const int base_r = R0 - 4;                          // >= 12

    const float4* px = reinterpret_cast<const float4*>(x) + ibase
                       + (size_t)base_r * W4 + g;
    const float4* py = reinterpret_cast<const float4*>(y) + ibase
                       + (size_t)base_r * W4 + g;
    const float gm = (g > 0) ? 1.f : 0.f;   // zero the g-1 stream for g==0

    // prefetch rings: depth 4 (g streams), depth 2 (g-1 streams)
    float4 bx[4], by[4], bxm[2], bym[2];
    #pragma unroll
    for (int k = 0; k < 4; ++k) { bx[k] = px[k * W4]; by[k] = py[k * W4]; }
    #pragma unroll
    for (int k = 0; k < 2; ++k) { bxm[k] = px[k * W4 - 1]; bym[k] = py[k * W4 - 1]; }

    float4 ring[5];
    #pragma unroll
    for (int k = 0; k < 5; ++k) ring[k] = f4zero();
    float4 vs = f4zero();
    float acc = 0.f;

    #pragma unroll
    for (int i = 0; i < SCAN; ++i) {
        const int s4 = i % 4;
        const int s2 = i % 2;
        const float4 a  = bx[s4];
        const float4 b  = by[s4];
        const float4 am = bxm[s2];
        const float4 bm = bym[s2];
        if (i + 4 < SCAN) {
            bx[s4] = px[(i + 4) * W4];
            by[s4] = py[(i + 4) * W4];
        }
        if (i + 2 < SCAN) {
            bxm[s2] = px[(i + 2) * W4 - 1];
            bym[s2] = py[(i + 2) * W4 - 1];
        }

        float4 cur, prv;
        cur.x = a.x - b.x; cur.y = a.y - b.y;
        cur.z = a.z - b.z; cur.w = a.w - b.w;
        prv.x = (am.x - bm.x) * gm; prv.y = (am.y - bm.y) * gm;
        prv.z = (am.z - bm.z) * gm; prv.w = (am.w - bm.w) * gm;

        float4 hv;
        const float p23 = prv.z + prv.w;
        const float c01 = cur.x + cur.y;
        hv.x = prv.x + prv.y + p23 + cur.x;
        hv.y = prv.y + p23 + c01;
        hv.z = p23 + c01 + cur.z;
        hv.w = prv.w + c01 + cur.z + cur.w;

        const int ph = i % 5;
        vs.x += hv.x - ring[ph].x; vs.y += hv.y - ring[ph].y;
        vs.z += hv.z - ring[ph].z; vs.w += hv.w - ring[ph].w;
        ring[ph] = hv;

        if (i >= 4)
            acc += fabsf(vs.x) + fabsf(vs.y) + fabsf(vs.z) + fabsf(vs.w);
    }

    reduce_finalize(acc, tid, lane, out);
}

// ================= boundary + edge kernel =================
__global__ void __launch_bounds__(THREADS)
box_boundary_kernel(const float* __restrict__ x, const float* __restrict__ y,
                    float* __restrict__ out) {
    const int tid  = threadIdx.x;
    const int lane = tid & 31;
    const int img  = blockIdx.y;
    const size_t ibase = (size_t)img * H * W4;
    const float4* x4 = reinterpret_cast<const float4*>(x) + ibase;
    const float4* y4 = reinterpret_cast<const float4*>(y) + ibase;

    float acc = 0.f;

    if (blockIdx.x < 2) {
        // boundary chunks: ci = 0 (top) and ci = 32 (bottom)
        const int ci     = (blockIdx.x == 0) ? 0 : (NCHUNK - 1);
        const int R0     = ci * CHUNK_ROWS;
        const int base_r = R0 - 4;
        const int imax   = min(SCAN - 1, OH - 1 - R0 + 4);

        const int g      = tid;
        const int gp     = (g > 0) ? (g - 1) : 0;
        const float gmask = (g > 0) ? 1.f : 0.f;

        float4 ring[5];
        #pragma unroll
        for (int k = 0; k < 5; ++k) ring[k] = f4zero();
        float4 vs = f4zero();

        #pragma unroll
        for (int i = 0; i < SCAN; ++i) {
            const int r = base_r + i;
            const int rc = min(max(r, 0), H - 1);
            const float rmask = (r >= 0 && r < H) ? 1.f : 0.f;
            const size_t ro = (size_t)rc * W4;
            const float4 a  = x4[ro + g];
            const float4 b  = y4[ro + g];
            const float4 ap = x4[ro + gp];
            const float4 bp = y4[ro + gp];

            float4 cur, prv;
            cur.x = (a.x - b.x) * rmask; cur.y = (a.y - b.y) * rmask;
            cur.z = (a.z - b.z) * rmask; cur.w = (a.w - b.w) * rmask;
            const float pm = gmask * rmask;
            prv.x = (ap.x - bp.x) * pm; prv.y = (ap.y - bp.y) * pm;
            prv.z = (ap.z - bp.z) * pm; prv.w = (ap.w - bp.w) * pm;

            float4 hv;
            const float p23 = prv.z + prv.w;
            const float c01 = cur.x + cur.y;
            hv.x = prv.x + prv.y + p23 + cur.x;
            hv.y = prv.y + p23 + c01;
            hv.z = p23 + c01 + cur.z;
            hv.w = prv.w + c01 + cur.z + cur.w;

            const int ph = i % 5;
            vs.x += hv.x - ring[ph].x; vs.y += hv.y - ring[ph].y;
            vs.z += hv.z - ring[ph].z; vs.w += hv.w - ring[ph].w;
            ring[ph] = hv;

            if (i >= 4 && i <= imax)
                acc += fabsf(vs.x) + fabsf(vs.y) + fabsf(vs.z) + fabsf(vs.w);
        }
    } else {
        // ---- edge path: output cols 512..515 (need only d-group 127) ----
        for (int pass = 0; pass < 2; ++pass) {
            if (pass == 1 && tid != 0) break;
            const int a = (pass == 0) ? 4 * tid : 512;
            float hx[8], hy[8], hz[8], hw[8];
            #pragma unroll
            for (int k = 0; k < 8; ++k) {
                const int r = a - 4 + k;
                float4 d = f4zero();
                if (r >= 0 && r < H) {
                    float4 av = x4[(size_t)r * W4 + 127];
                    float4 bv = y4[(size_t)r * W4 + 127];
                    d.x = av.x - bv.x; d.y = av.y - bv.y;
                    d.z = av.z - bv.z; d.w = av.w - bv.w;
                }
                hx[k] = d.x + d.y + d.z + d.w;   // h[512]
                hy[k] = d.y + d.z + d.w;         // h[513]
                hz[k] = d.z + d.w;               // h[514]
                hw[k] = d.w;                     // h[515]
            }
            #pragma unroll
            for (int j = 0; j < 4; ++j) {
                float sx = 0.f, sy = 0.f, sz = 0.f, sw = 0.f;
                #pragma unroll
                for (int k = j; k < j + 5; ++k) {
                    sx += hx[k]; sy += hy[k]; sz += hz[k]; sw += hw[k];
                }
                acc += fabsf(sx) + fabsf(sy) + fabsf(sz) + fabsf(sw);
            }
        }
    }

    reduce_finalize(acc, tid, lane, out);
}

extern "C" void kernel_launch(void* const* d_in, const int* in_sizes, int n_in,
                              void* d_out, int out_size) {
    (void)in_sizes; (void)n_in; (void)out_size;
    const float* x = (const float*)d_in[0];
    const float* y = (const float*)d_in[1];
    float* out = (float*)d_out;

    dim3 grid_a(NICHUNK, B_IMGS);
    dim3 grid_b(3, B_IMGS);
    box_interior_kernel<<<grid_a, THREADS>>>(x, y, out);
    box_boundary_kernel<<<grid_b, THREADS>>>(x, y, out);
}

// round 16
// speedup vs baseline: 1.3255x; 1.3255x over previous
#include <cuda_runtime.h>
#include <cuda_bf16.h>

// DataWindowLoss: mean(|box5(x) - box5(y)|), x,y: [64,1,512,512] f32.
// box5(x)-box5(y) = box5(x-y); separable 5x5 uniform kernel.
// Single-kernel register streaming with an EXPLICIT 85-reg budget
// (__launch_bounds__(128, 6)) so the prefetch rings (g-stream depth 4,
// g-1 stream depth 2) are not clamp-serialized by ptxas. Interior chunks
// take the unguarded hot loop; boundary chunks (0, 32) and cols 512..515
// run as guarded blocks in the SAME grid (no serial second launch).

#define B_IMGS 64
#define H 512
#define W 512
#define W4 128
#define OH 516
#define OW 516

#define THREADS 128
#define CHUNK_ROWS 16
#define SCAN 20
#define NCHUNK 33                        // 33*16 = 528 >= 516
#define NBLOCKS ((NCHUNK + 1) * B_IMGS)  // 2176

__device__ double g_accum;      // zero-initialized
__device__ unsigned g_count;    // zero-initialized

__device__ __forceinline__ float warp_red(float v) {
    #pragma unroll
    for (int o = 16; o > 0; o >>= 1) v += __shfl_down_sync(0xffffffffu, v, o);
    return v;
}

__device__ __forceinline__ float4 f4zero() { return make_float4(0.f, 0.f, 0.f, 0.f); }

__global__ void __launch_bounds__(THREADS, 6)
box_abs_kernel(const float* __restrict__ x, const float* __restrict__ y,
               float* __restrict__ out) {
    const int tid  = threadIdx.x;
    const int lane = tid & 31;
    const int img  = blockIdx.y;
    const size_t ibase = (size_t)img * H * W4;
    const float4* x4 = reinterpret_cast<const float4*>(x) + ibase;
    const float4* y4 = reinterpret_cast<const float4*>(y) + ibase;

    float acc = 0.f;

    if (blockIdx.x < NCHUNK) {
        const int ci     = blockIdx.x;
        const int R0     = ci * CHUNK_ROWS;
        const int base_r = R0 - 4;
        const bool interior = (base_r >= 0) && (base_r + SCAN - 1 < H);

        if (interior) {
            // ================= hot loop (unguarded) =================
            const int g = tid;
            const float4* px = x4 + (size_t)base_r * W4 + g;
            const float4* py = y4 + (size_t)base_r * W4 + g;
            const float gm = (g > 0) ? 1.f : 0.f;   // zero g-1 stream at g==0

            // prefetch rings: depth 4 (g streams), depth 2 (g-1 streams)
            float4 bx[4], by[4], bxm[2], bym[2];
            #pragma unroll
            for (int k = 0; k < 4; ++k) { bx[k] = px[k * W4]; by[k] = py[k * W4]; }
            #pragma unroll
            for (int k = 0; k < 2; ++k) { bxm[k] = px[k * W4 - 1]; bym[k] = py[k * W4 - 1]; }

            float4 ring[5];
            #pragma unroll
            for (int k = 0; k < 5; ++k) ring[k] = f4zero();
            float4 vs = f4zero();

            #pragma unroll
            for (int i = 0; i < SCAN; ++i) {
                const int s4 = i % 4;
                const int s2 = i % 2;
                const float4 a  = bx[s4];
                const float4 b  = by[s4];
                const float4 am = bxm[s2];
                const float4 bm = bym[s2];
                if (i + 4 < SCAN) {
                    bx[s4] = px[(i + 4) * W4];
                    by[s4] = py[(i + 4) * W4];
                }
                if (i + 2 < SCAN) {
                    bxm[s2] = px[(i + 2) * W4 - 1];
                    bym[s2] = py[(i + 2) * W4 - 1];
                }

                float4 cur, prv;
                cur.x = a.x - b.x; cur.y = a.y - b.y;
                cur.z = a.z - b.z; cur.w = a.w - b.w;
                prv.x = (am.x - bm.x) * gm; prv.y = (am.y - bm.y) * gm;
                prv.z = (am.z - bm.z) * gm; prv.w = (am.w - bm.w) * gm;

                float4 hv;
                const float p23 = prv.z + prv.w;
                const float c01 = cur.x + cur.y;
                hv.x = prv.x + prv.y + p23 + cur.x;
                hv.y = prv.y + p23 + c01;
                hv.z = p23 + c01 + cur.z;
                hv.w = prv.w + c01 + cur.z + cur.w;

                const int ph = i % 5;
                vs.x += hv.x - ring[ph].x; vs.y += hv.y - ring[ph].y;
                vs.z += hv.z - ring[ph].z; vs.w += hv.w - ring[ph].w;
                ring[ph] = hv;

                if (i >= 4)
                    acc += fabsf(vs.x) + fabsf(vs.y) + fabsf(vs.z) + fabsf(vs.w);
            }
        } else {
            // ================= guarded boundary chunk =================
            const int imax = min(SCAN - 1, OH - 1 - R0 + 4);
            const int g    = tid;
            const int gp   = (g > 0) ? (g - 1) : 0;
            const float gmask = (g > 0) ? 1.f : 0.f;

            float4 ring[5];
            #pragma unroll
            for (int k = 0; k < 5; ++k) ring[k] = f4zero();
            float4 vs = f4zero();

            #pragma unroll
            for (int i = 0; i < SCAN; ++i) {
                const int r = base_r + i;
                const int rc = min(max(r, 0), H - 1);
                const float rmask = (r >= 0 && r < H) ? 1.f : 0.f;
                const size_t ro = (size_t)rc * W4;
                const float4 a  = x4[ro + g];
                const float4 b  = y4[ro + g];
                const float4 ap = x4[ro + gp];
                const float4 bp = y4[ro + gp];

                float4 cur, prv;
                cur.x = (a.x - b.x) * rmask; cur.y = (a.y - b.y) * rmask;
                cur.z = (a.z - b.z) * rmask; cur.w = (a.w - b.w) * rmask;
                const float pm = gmask * rmask;
                prv.x = (ap.x - bp.x) * pm; prv.y = (ap.y - bp.y) * pm;
                prv.z = (ap.z - bp.z) * pm; prv.w = (ap.w - bp.w) * pm;

                float4 hv;
                const float p23 = prv.z + prv.w;
                const float c01 = cur.x + cur.y;
                hv.x = prv.x + prv.y + p23 + cur.x;
                hv.y = prv.y + p23 + c01;
                hv.z = p23 + c01 + cur.z;
                hv.w = prv.w + c01 + cur.z + cur.w;

                const int ph = i % 5;
                vs.x += hv.x - ring[ph].x; vs.y += hv.y - ring[ph].y;
                vs.z += hv.z - ring[ph].z; vs.w += hv.w - ring[ph].w;
                ring[ph] = hv;

                if (i >= 4 && i <= imax)
                    acc += fabsf(vs.x) + fabsf(vs.y) + fabsf(vs.z) + fabsf(vs.w);
            }
        }
    } else {
        // ---- edge path: output cols 512..515 (need only d-group 127) ----
        for (int pass = 0; pass < 2; ++pass) {
            if (pass == 1 && tid != 0) break;
            const int a = (pass == 0) ? 4 * tid : 512;
            float hx[8], hy[8], hz[8], hw[8];
            #pragma unroll
            for (int k = 0; k < 8; ++k) {
                const int r = a - 4 + k;
                float4 d = f4zero();
                if (r >= 0 && r < H) {
                    float4 av = x4[(size_t)r * W4 + 127];
                    float4 bv = y4[(size_t)r * W4 + 127];
                    d.x = av.x - bv.x; d.y = av.y - bv.y;
                    d.z = av.z - bv.z; d.w = av.w - bv.w;
                }
                hx[k] = d.x + d.y + d.z + d.w;   // h[512]
                hy[k] = d.y + d.z + d.w;         // h[513]
                hz[k] = d.z + d.w;               // h[514]
                hw[k] = d.w;                     // h[515]
            }
            #pragma unroll
            for (int j = 0; j < 4; ++j) {
                float sx = 0.f, sy = 0.f, sz = 0.f, sw = 0.f;
                #pragma unroll
                for (int k = j; k < j + 5; ++k) {
                    sx += hx[k]; sy += hy[k]; sz += hz[k]; sw += hw[k];
                }
                acc += fabsf(sx) + fabsf(sy) + fabsf(sz) + fabsf(sw);
            }
        }
    }

    // ---- block reduce + fused finalize ----
    __shared__ float wsum[THREADS / 32];
    acc = warp_red(acc);
    if (lane == 0) wsum[tid >> 5] = acc;
    __syncthreads();
    if (tid == 0) {
        float v = 0.f;
        #pragma unroll
        for (int i = 0; i < THREADS / 32; ++i) v += wsum[i];
        atomicAdd(&g_accum, (double)v);
        __threadfence();
        unsigned prev_cnt = atomicAdd(&g_count, 1u);
        if (prev_cnt == NBLOCKS - 1) {
            __threadfence();
            double total = atomicAdd(&g_accum, 0.0);
            const double scale = 1.0 / (25.0 * (double)B_IMGS * (double)OH * (double)OW);
            out[0] = (float)(total * scale);
            g_accum = 0.0;          // reset for next graph replay
            __threadfence();
            g_count = 0u;
        }
    }
}

extern "C" void kernel_launch(void* const* d_in, const int* in_sizes, int n_in,
                              void* d_out, int out_size) {
    (void)in_sizes; (void)n_in; (void)out_size;
    const float* x = (const float*)d_in[0];
    const float* y = (const float*)d_in[1];
    float* out = (float*)d_out;

    dim3 grid(NCHUNK + 1, B_IMGS);
    box_abs_kernel<<<grid, THREADS>>>(x, y, out);
}

// round 17
// speedup vs baseline: 1.4303x; 1.0790x over previous
#include <cuda_runtime.h>
#include <cuda_bf16.h>

// DataWindowLoss: mean(|box5(x) - box5(y)|), x,y: [64,1,512,512] f32.
// box5(x)-box5(y) = box5(x-y); separable 5x5 uniform kernel.
// Register streaming: g-stream prefetch ring depth 4 (true MLP under a
// 73-reg budget via __launch_bounds__(128,7) -> 7 blocks/SM, 28 warps);
// the g-1 neighbor loads are issued AT CONSUME TIME and hit L1 (their
// line was fetched by the same row's g load). Interior chunks unguarded;
// boundary chunks (0, 32) + cols 512..515 guarded, same grid.

#define B_IMGS 64
#define H 512
#define W 512
#define W4 128
#define OH 516
#define OW 516

#define THREADS 128
#define CHUNK_ROWS 16
#define SCAN 20
#define NCHUNK 33                        // 33*16 = 528 >= 516
#define NBLOCKS ((NCHUNK + 1) * B_IMGS)  // 2176

__device__ double g_accum;      // zero-initialized
__device__ unsigned g_count;    // zero-initialized

__device__ __forceinline__ float warp_red(float v) {
    #pragma unroll
    for (int o = 16; o > 0; o >>= 1) v += __shfl_down_sync(0xffffffffu, v, o);
    return v;
}

__device__ __forceinline__ float4 f4zero() { return make_float4(0.f, 0.f, 0.f, 0.f); }

__global__ void __launch_bounds__(THREADS, 7)
box_abs_kernel(const float* __restrict__ x, const float* __restrict__ y,
               float* __restrict__ out) {
    const int tid  = threadIdx.x;
    const int lane = tid & 31;
    const int img  = blockIdx.y;
    const size_t ibase = (size_t)img * H * W4;
    const float4* x4 = reinterpret_cast<const float4*>(x) + ibase;
    const float4* y4 = reinterpret_cast<const float4*>(y) + ibase;

    float acc = 0.f;

    if (blockIdx.x < NCHUNK) {
        const int ci     = blockIdx.x;
        const int R0     = ci * CHUNK_ROWS;
        const int base_r = R0 - 4;
        const bool interior = (base_r >= 0) && (base_r + SCAN - 1 < H);

        if (interior) {
            // ================= hot loop (unguarded) =================
            const int g = tid;
            const float4* px = x4 + (size_t)base_r * W4 + g;
            const float4* py = y4 + (size_t)base_r * W4 + g;
            const float gm = (g > 0) ? 1.f : 0.f;   // zero g-1 stream at g==0

            // prefetch ring: depth 4 (g streams only)
            float4 bx[4], by[4];
            #pragma unroll
            for (int k = 0; k < 4; ++k) { bx[k] = px[k * W4]; by[k] = py[k * W4]; }

            float4 ring[5];
            #pragma unroll
            for (int k = 0; k < 5; ++k) ring[k] = f4zero();
            float4 vs = f4zero();

            #pragma unroll
            for (int i = 0; i < SCAN; ++i) {
                const int s4 = i % 4;
                const float4 a = bx[s4];
                const float4 b = by[s4];
                if (i + 4 < SCAN) {
                    bx[s4] = px[(i + 4) * W4];
                    by[s4] = py[(i + 4) * W4];
                }
                // g-1 neighbor: L1 hit (line fetched by this row's g load;
                // g==0 reads prev row's last group -- in-bounds, masked)
                const float4 am = px[i * W4 - 1];
                const float4 bm = py[i * W4 - 1];

                float4 cur, prv;
                cur.x = a.x - b.x; cur.y = a.y - b.y;
                cur.z = a.z - b.z; cur.w = a.w - b.w;
                prv.x = (am.x - bm.x) * gm; prv.y = (am.y - bm.y) * gm;
                prv.z = (am.z - bm.z) * gm; prv.w = (am.w - bm.w) * gm;

                float4 hv;
                const float p23 = prv.z + prv.w;
                const float c01 = cur.x + cur.y;
                hv.x = prv.x + prv.y + p23 + cur.x;
                hv.y = prv.y + p23 + c01;
                hv.z = p23 + c01 + cur.z;
                hv.w = prv.w + c01 + cur.z + cur.w;

                const int ph = i % 5;
                vs.x += hv.x - ring[ph].x; vs.y += hv.y - ring[ph].y;
                vs.z += hv.z - ring[ph].z; vs.w += hv.w - ring[ph].w;
                ring[ph] = hv;

                if (i >= 4)
                    acc += fabsf(vs.x) + fabsf(vs.y) + fabsf(vs.z) + fabsf(vs.w);
            }
        } else {
            // ================= guarded boundary chunk =================
            const int imax = min(SCAN - 1, OH - 1 - R0 + 4);
            const int g    = tid;
            const int gp   = (g > 0) ? (g - 1) : 0;
            const float gmask = (g > 0) ? 1.f : 0.f;

            float4 ring[5];
            #pragma unroll
            for (int k = 0; k < 5; ++k) ring[k] = f4zero();
            float4 vs = f4zero();

            #pragma unroll
            for (int i = 0; i < SCAN; ++i) {
                const int r = base_r + i;
                const int rc = min(max(r, 0), H - 1);
                const float rmask = (r >= 0 && r < H) ? 1.f : 0.f;
                const size_t ro = (size_t)rc * W4;
                const float4 a  = x4[ro + g];
                const float4 b  = y4[ro + g];
                const float4 ap = x4[ro + gp];
                const float4 bp = y4[ro + gp];

                float4 cur, prv;
                cur.x = (a.x - b.x) * rmask; cur.y = (a.y - b.y) * rmask;
                cur.z = (a.z - b.z) * rmask; cur.w = (a.w - b.w) * rmask;
                const float pm = gmask * rmask;
                prv.x = (ap.x - bp.x) * pm; prv.y = (ap.y - bp.y) * pm;
                prv.z = (ap.z - bp.z) * pm; prv.w = (ap.w - bp.w) * pm;

                float4 hv;
                const float p23 = prv.z + prv.w;
                const float c01 = cur.x + cur.y;
                hv.x = prv.x + prv.y + p23 + cur.x;
                hv.y = prv.y + p23 + c01;
                hv.z = p23 + c01 + cur.z;
                hv.w = prv.w + c01 + cur.z + cur.w;

                const int ph = i % 5;
                vs.x += hv.x - ring[ph].x; vs.y += hv.y - ring[ph].y;
                vs.z += hv.z - ring[ph].z; vs.w += hv.w - ring[ph].w;
                ring[ph] = hv;

                if (i >= 4 && i <= imax)
                    acc += fabsf(vs.x) + fabsf(vs.y) + fabsf(vs.z) + fabsf(vs.w);
            }
        }
    } else {
        // ---- edge path: output cols 512..515 (need only d-group 127) ----
        for (int pass = 0; pass < 2; ++pass) {
            if (pass == 1 && tid != 0) break;
            const int a = (pass == 0) ? 4 * tid : 512;
            float hx[8], hy[8], hz[8], hw[8];
            #pragma unroll
            for (int k = 0; k < 8; ++k) {
                const int r = a - 4 + k;
                float4 d = f4zero();
                if (r >= 0 && r < H) {
                    float4 av = x4[(size_t)r * W4 + 127];
                    float4 bv = y4[(size_t)r * W4 + 127];
                    d.x = av.x - bv.x; d.y = av.y - bv.y;
                    d.z = av.z - bv.z; d.w = av.w - bv.w;
                }
                hx[k] = d.x + d.y + d.z + d.w;   // h[512]
                hy[k] = d.y + d.z + d.w;         // h[513]
                hz[k] = d.z + d.w;               // h[514]
                hw[k] = d.w;                     // h[515]
            }
            #pragma unroll
            for (int j = 0; j < 4; ++j) {
                float sx = 0.f, sy = 0.f, sz = 0.f, sw = 0.f;
                #pragma unroll
                for (int k = j; k < j + 5; ++k) {
                    sx += hx[k]; sy += hy[k]; sz += hz[k]; sw += hw[k];
                }
                acc += fabsf(sx) + fabsf(sy) + fabsf(sz) + fabsf(sw);
            }
        }
    }

    // ---- block reduce + fused finalize ----
    __shared__ float wsum[THREADS / 32];
    acc = warp_red(acc);
    if (lane == 0) wsum[tid >> 5] = acc;
    __syncthreads();
    if (tid == 0) {
        float v = 0.f;
        #pragma unroll
        for (int i = 0; i < THREADS / 32; ++i) v += wsum[i];
        atomicAdd(&g_accum, (double)v);
        __threadfence();
        unsigned prev_cnt = atomicAdd(&g_count, 1u);
        if (prev_cnt == NBLOCKS - 1) {
            __threadfence();
            double total = atomicAdd(&g_accum, 0.0);
            const double scale = 1.0 / (25.0 * (double)B_IMGS * (double)OH * (double)OW);
            out[0] = (float)(total * scale);
            g_accum = 0.0;          // reset for next graph replay
            __threadfence();
            g_count = 0u;
        }
    }
}

extern "C" void kernel_launch(void* const* d_in, const int* in_sizes, int n_in,
                              void* d_out, int out_size) {
    (void)in_sizes; (void)n_in; (void)out_size;
    const float* x = (const float*)d_in[0];
    const float* y = (const float*)d_in[1];
    float* out = (float*)d_out;

    dim3 grid(NCHUNK + 1, B_IMGS);
    box_abs_kernel<<<grid, THREADS>>>(x, y, out);
}